// round 9
// baseline (speedup 1.0000x reference)
#include <cuda_runtime.h>
#include <cstdint>

#define NN 100000
#define NE 1600000

// ---------------- scratch (device globals: no allocation allowed) ----------------
__device__ float g_Pd[NN * 64];     // x @ W1[0:64]   + b1   (gathered by dst)
__device__ float g_Ps[NN * 64];     // x @ W1[64:128]        (gathered by src)
__device__ float g_agg[NN * 64];    // segment-sum accumulator
__device__ float g_zp[NN * 64];     // pre-BN activations
__device__ float g_stats[128];      // [0:64) column sums, [64:128) column sumsq
__device__ int   g_is64;            // edge_index dtype flag

__device__ __forceinline__ float prelu(float v, float a) { return v >= 0.f ? v : a * v; }

// ---------------- detect edge_index dtype (int64 vs int32) ----------------
__global__ void k_detect(const long long* ei) {
    if (threadIdx.x == 0) {
        int ok = 1;
        for (int i = 0; i < 64; i++) {
            long long v = ei[i];
            if (v < 0 || v >= NN) { ok = 0; break; }
        }
        g_is64 = ok;   // int32 data reinterpreted as int64 fails range check w.p. ~1
    }
}

// ---------------- zero agg + stats ----------------
__global__ void k_zero() {
    int i = blockIdx.x * blockDim.x + threadIdx.x;
    int stride = gridDim.x * blockDim.x;
    for (; i < NN * 64; i += stride) g_agg[i] = 0.f;
    if (blockIdx.x == 0 && threadIdx.x < 128) g_stats[threadIdx.x] = 0.f;
}

// ---------------- node pre-GEMM: Pd / Ps (k-pair packed weights, f32x2 math) ------
__global__ void __launch_bounds__(256) k_node_pre(const float* __restrict__ x,
                                                  const float* __restrict__ W1,
                                                  const float* __restrict__ b1) {
    __shared__ float Wp[32 * 256];   // 8192 floats, packed k-pairs
    __shared__ float xs[16 * 66];
    int t = threadIdx.x;
    int nb = blockIdx.x * 16;

    for (int idx = t; idx < 8192; idx += 256) {
        int k = idx >> 7, jc = idx & 127;
        float w = (jc < 64) ? W1[k * 64 + jc] : W1[(64 + k) * 64 + (jc - 64)];
        Wp[(k >> 1) * 256 + jc * 2 + (k & 1)] = w;
    }
    for (int idx = t; idx < 16 * 64; idx += 256) {
        int n = idx >> 6, k = idx & 63;
        xs[n * 66 + k] = x[(nb + n) * 64 + k];
    }
    __syncthreads();

    int node = t & 15;
    int jg   = t >> 4;       // 0..15 -> jc = jg*8
    unsigned long long acc[8];
#pragma unroll
    for (int i = 0; i < 8; i++) acc[i] = 0ULL;

    const float2* xrow = (const float2*)(xs + node * 66);
#pragma unroll
    for (int k2 = 0; k2 < 32; k2++) {
        float2 xv = xrow[k2];
        unsigned long long xp;
        asm("mov.b64 %0, {%1, %2};" : "=l"(xp) : "f"(xv.x), "f"(xv.y));
        const ulonglong2* wp = (const ulonglong2*)(Wp + k2 * 256 + jg * 16);
        ulonglong2 w0 = wp[0], w1 = wp[1], w2v = wp[2], w3v = wp[3];
        asm("fma.rn.f32x2 %0, %1, %2, %0;" : "+l"(acc[0]) : "l"(xp), "l"(w0.x));
        asm("fma.rn.f32x2 %0, %1, %2, %0;" : "+l"(acc[1]) : "l"(xp), "l"(w0.y));
        asm("fma.rn.f32x2 %0, %1, %2, %0;" : "+l"(acc[2]) : "l"(xp), "l"(w1.x));
        asm("fma.rn.f32x2 %0, %1, %2, %0;" : "+l"(acc[3]) : "l"(xp), "l"(w1.y));
        asm("fma.rn.f32x2 %0, %1, %2, %0;" : "+l"(acc[4]) : "l"(xp), "l"(w2v.x));
        asm("fma.rn.f32x2 %0, %1, %2, %0;" : "+l"(acc[5]) : "l"(xp), "l"(w2v.y));
        asm("fma.rn.f32x2 %0, %1, %2, %0;" : "+l"(acc[6]) : "l"(xp), "l"(w3v.x));
        asm("fma.rn.f32x2 %0, %1, %2, %0;" : "+l"(acc[7]) : "l"(xp), "l"(w3v.y));
    }

    float r[8];
#pragma unroll
    for (int i = 0; i < 8; i++) {
        float lo, hi;
        asm("mov.b64 {%0, %1}, %2;" : "=f"(lo), "=f"(hi) : "l"(acc[i]));
        r[i] = lo + hi;
    }
    int gnode = nb + node;
    int jc = jg * 8;
    if (jc < 64) {
#pragma unroll
        for (int i = 0; i < 8; i++) g_Pd[gnode * 64 + jc + i] = r[i] + b1[jc + i];
    } else {
        int jj = jc - 64;
#pragma unroll
        for (int i = 0; i < 8; i++) g_Ps[gnode * 64 + jj + i] = r[i];
    }
}

// ---------------- edge kernel: register-tiled 4-edge x 16-output blocks ----------
// 256 threads, 256 edges/block. Warp = 32 edges, laned as 8 edge-groups x 4 j-groups.
// Each thread: 4 edges x 16 outputs. h loads are float2 (stride-66 rows are only
// 8B-aligned). W2 stored in 80-float rows with jg-chunk at k*80 + jg*20 so the
// four 16B weight reads per instruction hit disjoint bank quads (conflict-free).
__global__ void __launch_bounds__(256, 2) k_edge(const void* eiv,
                                                 const float* __restrict__ W2,
                                                 const float* __restrict__ b2,
                                                 const float* __restrict__ A1,
                                                 const float* __restrict__ A2) {
    extern __shared__ float sm[];
    float* w2s = sm;          // 64 rows * 80 floats = 5120 (chunk jg at k*80+jg*20)
    float* b2s = sm + 5120;   // 64
    float* hs  = sm + 5184;   // 8 warps * 32 edges * 66 floats

    int t = threadIdx.x;
    for (int idx = t; idx < 4096; idx += 256) {
        int k = idx >> 6, j = idx & 63;
        w2s[k * 80 + (j >> 4) * 20 + (j & 15)] = W2[idx];
    }
    if (t < 64) b2s[t] = b2[t];
    float a1 = A1[0], a2 = A2[0];

    int e = blockIdx.x * 256 + t;           // grid = NE/256 exactly
    long long my_src, my_dst;
    if (g_is64) {
        const long long* ei = (const long long*)eiv;
        my_src = ei[e];
        my_dst = ei[NE + e];
    } else {
        const int* ei = (const int*)eiv;
        my_src = (long long)ei[e];
        my_dst = (long long)ei[NE + e];
    }
    __syncthreads();

    int lane = t & 31;
    float* hsw = hs + (t >> 5) * (32 * 66);

    // Cooperative gather: whole warp loads one edge's 64-wide Pd[dst]+Ps[src]
    // coalesced, applies prelu(a1), stages row to smem (stride 66).
#pragma unroll 1
    for (int ee = 0; ee < 32; ee++) {
        long long d = __shfl_sync(0xffffffffu, my_dst, ee);
        long long s = __shfl_sync(0xffffffffu, my_src, ee);
        const float2* pd2 = (const float2*)(g_Pd + d * 64);
        const float2* ps2 = (const float2*)(g_Ps + s * 64);
        float2 a = pd2[lane];
        float2 b = ps2[lane];
        float v0 = prelu(a.x + b.x, a1);
        float v1 = prelu(a.y + b.y, a1);
        ((float2*)(hsw + ee * 66))[lane] = make_float2(v0, v1);
    }
    __syncwarp();

    int eg = lane >> 2;        // 0..7: edge group (edges eg*4 .. eg*4+3)
    int jg = lane & 3;         // 0..3: output group (j = jg*16 .. jg*16+15)

    unsigned long long acc[4][8];
#pragma unroll
    for (int i = 0; i < 4; i++)
#pragma unroll
        for (int jj = 0; jj < 8; jj++) acc[i][jj] = 0ULL;

    const float* wbase = w2s + jg * 20;
    const float* hbase = hsw + eg * 4 * 66;

#pragma unroll 2
    for (int k4 = 0; k4 < 16; k4++) {
        // 4 edges x 4 k-values, loaded as float2 pairs (8B-aligned everywhere)
        float2 ha[4], hb[4];
#pragma unroll
        for (int i = 0; i < 4; i++) {
            ha[i] = *(const float2*)(hbase + i * 66 + k4 * 4);
            hb[i] = *(const float2*)(hbase + i * 66 + k4 * 4 + 2);
        }
#pragma unroll
        for (int kk = 0; kk < 4; kk++) {
            const ulonglong2* w = (const ulonglong2*)(wbase + (k4 * 4 + kk) * 80);
            ulonglong2 w0 = w[0], w1 = w[1];   // 16 weight floats, 4x LDS.128
            unsigned long long hp[4];
#pragma unroll
            for (int i = 0; i < 4; i++) {
                float hk = (kk == 0) ? ha[i].x : (kk == 1) ? ha[i].y
                         : (kk == 2) ? hb[i].x : hb[i].y;
                asm("mov.b64 %0, {%1, %1};" : "=l"(hp[i]) : "f"(hk));
            }
#pragma unroll
            for (int i = 0; i < 4; i++) {
                asm("fma.rn.f32x2 %0, %1, %2, %0;" : "+l"(acc[i][0]) : "l"(hp[i]), "l"(w0.x));
                asm("fma.rn.f32x2 %0, %1, %2, %0;" : "+l"(acc[i][1]) : "l"(hp[i]), "l"(w0.y));
                asm("fma.rn.f32x2 %0, %1, %2, %0;" : "+l"(acc[i][2]) : "l"(hp[i]), "l"(w1.x));
                asm("fma.rn.f32x2 %0, %1, %2, %0;" : "+l"(acc[i][3]) : "l"(hp[i]), "l"(w1.y));
            }
            const ulonglong2* w2p = w + 2;
            ulonglong2 w2v = w2p[0], w3v = w2p[1];
#pragma unroll
            for (int i = 0; i < 4; i++) {
                asm("fma.rn.f32x2 %0, %1, %2, %0;" : "+l"(acc[i][4]) : "l"(hp[i]), "l"(w2v.x));
                asm("fma.rn.f32x2 %0, %1, %2, %0;" : "+l"(acc[i][5]) : "l"(hp[i]), "l"(w2v.y));
                asm("fma.rn.f32x2 %0, %1, %2, %0;" : "+l"(acc[i][6]) : "l"(hp[i]), "l"(w3v.x));
                asm("fma.rn.f32x2 %0, %1, %2, %0;" : "+l"(acc[i][7]) : "l"(hp[i]), "l"(w3v.y));
            }
        }
    }

    // Epilogue: bias + prelu(a2) + scatter-reduce. Each (edge, j16-block) owned by
    // exactly one thread -> 4 red.v4 per edge slice, 16 per thread.
    float bj[16];
#pragma unroll
    for (int q = 0; q < 16; q++) bj[q] = b2s[jg * 16 + q];

#pragma unroll
    for (int i = 0; i < 4; i++) {
        long long d = __shfl_sync(0xffffffffu, my_dst, eg * 4 + i);
        float* aggp = g_agg + d * 64 + jg * 16;
        float r[16];
#pragma unroll
        for (int jj = 0; jj < 8; jj++) {
            float lo, hi;
            asm("mov.b64 {%0, %1}, %2;" : "=f"(lo), "=f"(hi) : "l"(acc[i][jj]));
            r[2 * jj]     = prelu(lo + bj[2 * jj], a2);
            r[2 * jj + 1] = prelu(hi + bj[2 * jj + 1], a2);
        }
#pragma unroll
        for (int q = 0; q < 4; q++)
            asm volatile("red.global.add.v4.f32 [%0], {%1, %2, %3, %4};" ::
                         "l"(aggp + q * 4),
                         "f"(r[4 * q]), "f"(r[4 * q + 1]),
                         "f"(r[4 * q + 2]), "f"(r[4 * q + 3]));
    }
}

// ---------------- node MLP + block prelu + BN partial stats (packed weights) ------
__global__ void __launch_bounds__(256) k_node(const float* __restrict__ x,
                                              const float* __restrict__ W3,
                                              const float* __restrict__ b3,
                                              const float* __restrict__ A3,
                                              const float* __restrict__ W4,
                                              const float* __restrict__ b4,
                                              const float* __restrict__ Ablk) {
    extern __shared__ float sm[];
    float* ms  = sm;                         // 32*130 = 4160
    float* W3p = sm + 4160;                  // 8192: [(k/2)*128 + j*2 + (k&1)]
    float* W4p = sm + 4160 + 8192;           // 4096
    float* z1s = sm + 4160 + 8192 + 4096;    // 32*66 = 2112

    int t = threadIdx.x;
    int nb = blockIdx.x * 32;
    for (int idx = t; idx < 8192; idx += 256) {
        int k = idx >> 6, j = idx & 63;
        W3p[(k >> 1) * 128 + j * 2 + (k & 1)] = W3[idx];
    }
    for (int idx = t; idx < 4096; idx += 256) {
        int k = idx >> 6, j = idx & 63;
        W4p[(k >> 1) * 128 + j * 2 + (k & 1)] = W4[idx];
    }
    for (int idx = t; idx < 2048; idx += 256) {
        int n = idx >> 6, k = idx & 63;
        ms[n * 130 + k]      = x[(nb + n) * 64 + k];
        ms[n * 130 + 64 + k] = g_agg[(nb + n) * 64 + k];
    }
    float a3 = A3[0], ab = Ablk[0];
    __syncthreads();

    int node = t & 31;
    int jg   = t >> 5;   // 0..7
    unsigned long long acc[8];
#pragma unroll
    for (int i = 0; i < 8; i++) acc[i] = 0ULL;

    const float2* mrow = (const float2*)(ms + node * 130);
#pragma unroll 8
    for (int k2 = 0; k2 < 64; k2++) {
        float2 mv = mrow[k2];
        unsigned long long mp;
        asm("mov.b64 %0, {%1, %2};" : "=l"(mp) : "f"(mv.x), "f"(mv.y));
        const ulonglong2* wp = (const ulonglong2*)(W3p + k2 * 128 + jg * 16);
        ulonglong2 w0 = wp[0], w1 = wp[1], w2v = wp[2], w3v = wp[3];
        asm("fma.rn.f32x2 %0, %1, %2, %0;" : "+l"(acc[0]) : "l"(mp), "l"(w0.x));
        asm("fma.rn.f32x2 %0, %1, %2, %0;" : "+l"(acc[1]) : "l"(mp), "l"(w0.y));
        asm("fma.rn.f32x2 %0, %1, %2, %0;" : "+l"(acc[2]) : "l"(mp), "l"(w1.x));
        asm("fma.rn.f32x2 %0, %1, %2, %0;" : "+l"(acc[3]) : "l"(mp), "l"(w1.y));
        asm("fma.rn.f32x2 %0, %1, %2, %0;" : "+l"(acc[4]) : "l"(mp), "l"(w2v.x));
        asm("fma.rn.f32x2 %0, %1, %2, %0;" : "+l"(acc[5]) : "l"(mp), "l"(w2v.y));
        asm("fma.rn.f32x2 %0, %1, %2, %0;" : "+l"(acc[6]) : "l"(mp), "l"(w3v.x));
        asm("fma.rn.f32x2 %0, %1, %2, %0;" : "+l"(acc[7]) : "l"(mp), "l"(w3v.y));
    }
    {
        float2* zrow = (float2*)(z1s + node * 66);
#pragma unroll
        for (int i2 = 0; i2 < 4; i2++) {
            float l0, h0, l1, h1;
            asm("mov.b64 {%0, %1}, %2;" : "=f"(l0), "=f"(h0) : "l"(acc[2 * i2]));
            asm("mov.b64 {%0, %1}, %2;" : "=f"(l1), "=f"(h1) : "l"(acc[2 * i2 + 1]));
            int j = jg * 8 + 2 * i2;
            zrow[jg * 4 + i2] = make_float2(prelu(l0 + h0 + b3[j], a3),
                                            prelu(l1 + h1 + b3[j + 1], a3));
        }
    }
    __syncthreads();

#pragma unroll
    for (int i = 0; i < 8; i++) acc[i] = 0ULL;
    const float2* zr = (const float2*)(z1s + node * 66);
#pragma unroll 8
    for (int k2 = 0; k2 < 32; k2++) {
        float2 zv = zr[k2];
        unsigned long long zpk;
        asm("mov.b64 %0, {%1, %2};" : "=l"(zpk) : "f"(zv.x), "f"(zv.y));
        const ulonglong2* wp = (const ulonglong2*)(W4p + k2 * 128 + jg * 16);
        ulonglong2 w0 = wp[0], w1 = wp[1], w2v = wp[2], w3v = wp[3];
        asm("fma.rn.f32x2 %0, %1, %2, %0;" : "+l"(acc[0]) : "l"(zpk), "l"(w0.x));
        asm("fma.rn.f32x2 %0, %1, %2, %0;" : "+l"(acc[1]) : "l"(zpk), "l"(w0.y));
        asm("fma.rn.f32x2 %0, %1, %2, %0;" : "+l"(acc[2]) : "l"(zpk), "l"(w1.x));
        asm("fma.rn.f32x2 %0, %1, %2, %0;" : "+l"(acc[3]) : "l"(zpk), "l"(w1.y));
        asm("fma.rn.f32x2 %0, %1, %2, %0;" : "+l"(acc[4]) : "l"(zpk), "l"(w2v.x));
        asm("fma.rn.f32x2 %0, %1, %2, %0;" : "+l"(acc[5]) : "l"(zpk), "l"(w2v.y));
        asm("fma.rn.f32x2 %0, %1, %2, %0;" : "+l"(acc[6]) : "l"(zpk), "l"(w3v.x));
        asm("fma.rn.f32x2 %0, %1, %2, %0;" : "+l"(acc[7]) : "l"(zpk), "l"(w3v.y));
    }

    float zp[8], sq[8];
#pragma unroll
    for (int i = 0; i < 8; i++) {
        float lo, hi;
        asm("mov.b64 {%0, %1}, %2;" : "=f"(lo), "=f"(hi) : "l"(acc[i]));
        zp[i] = prelu(lo + hi + b4[jg * 8 + i], ab);
        sq[i] = zp[i] * zp[i];
    }
    int gnode = nb + node;
    float4* o4 = (float4*)(g_zp + gnode * 64 + jg * 8);
    o4[0] = make_float4(zp[0], zp[1], zp[2], zp[3]);
    o4[1] = make_float4(zp[4], zp[5], zp[6], zp[7]);

    float s[8];
#pragma unroll
    for (int i = 0; i < 8; i++) s[i] = zp[i];
#pragma unroll
    for (int o = 16; o > 0; o >>= 1) {
#pragma unroll
        for (int i = 0; i < 8; i++) {
            s[i]  += __shfl_xor_sync(0xffffffffu, s[i], o);
            sq[i] += __shfl_xor_sync(0xffffffffu, sq[i], o);
        }
    }
    if ((t & 31) == 0) {
        int j = jg * 8;
#pragma unroll
        for (int i = 0; i < 8; i++) {
            atomicAdd(&g_stats[j + i], s[i]);
            atomicAdd(&g_stats[64 + j + i], sq[i]);
        }
    }
}

// ---------------- BN finalize ----------------
__global__ void __launch_bounds__(256) k_finalize(const float* __restrict__ gamma,
                                                  const float* __restrict__ beta,
                                                  float* __restrict__ out) {
    int i0 = blockIdx.x * blockDim.x + threadIdx.x;
    int stride = gridDim.x * blockDim.x;   // 65536, multiple of 64 -> j fixed per thread
    int j = i0 & 63;
    const float invN = 1.0f / NN;
    float mean  = g_stats[j] * invN;
    float var   = g_stats[64 + j] * invN - mean * mean;
    float scale = rsqrtf(var + 1e-5f) * gamma[j];
    float bias  = beta[j] - mean * scale;
    for (int i = i0; i < NN * 64; i += stride)
        out[i] = g_zp[i] * scale + bias;
}

// ---------------- launch ----------------
extern "C" void kernel_launch(void* const* d_in, const int* in_sizes, int n_in,
                              void* d_out, int out_size) {
    const float* x     = (const float*)d_in[0];
    const void*  ei    = d_in[1];
    const float* W1    = (const float*)d_in[2];
    const float* b1    = (const float*)d_in[3];
    const float* a1    = (const float*)d_in[4];
    const float* W2    = (const float*)d_in[5];
    const float* b2    = (const float*)d_in[6];
    const float* a2    = (const float*)d_in[7];
    const float* W3    = (const float*)d_in[8];
    const float* b3    = (const float*)d_in[9];
    const float* a3    = (const float*)d_in[10];
    const float* W4    = (const float*)d_in[11];
    const float* b4    = (const float*)d_in[12];
    const float* ablk  = (const float*)d_in[13];
    const float* gamma = (const float*)d_in[14];
    const float* beta  = (const float*)d_in[15];
    float* out = (float*)d_out;

    const int EDGE_SMEM = (5184 + 8 * 32 * 66) * 4;                  // 88320 B
    const int NODE_SMEM = (4160 + 8192 + 4096 + 32 * 66) * 4;        // 74240 B
    cudaFuncSetAttribute(k_edge, cudaFuncAttributeMaxDynamicSharedMemorySize, EDGE_SMEM);
    cudaFuncSetAttribute(k_node, cudaFuncAttributeMaxDynamicSharedMemorySize, NODE_SMEM);

    k_detect<<<1, 32>>>((const long long*)ei);
    k_zero<<<2048, 256>>>();
    k_node_pre<<<NN / 16, 256>>>(x, W1, b1);                  // 6250 blocks (exact)
    k_edge<<<NE / 256, 256, EDGE_SMEM>>>(ei, W2, b2, a1, a2); // 6250 blocks (exact)
    k_node<<<NN / 32, 256, NODE_SMEM>>>(x, W3, b3, a3, W4, b4, ablk); // 3125 blocks (exact)
    k_finalize<<<256, 256>>>(gamma, beta, out);
}